// round 5
// baseline (speedup 1.0000x reference)
#include <cuda_runtime.h>
#include <cuda_fp16.h>
#include <cstdint>

// ---------------- problem constants ----------------
#define BROWS 10240          // B*N = 2048*5
#define HID   2048
#define OUTD  512
#define PLANE ((size_t)BROWS * HID)

// ---------------- persistent device scratch ----------------
// 5 DFT planes: [0]=X0, [1]=X2, [2]=Xs(=Xr+Xi), [3]=Xr, [4]=Xi
__device__ __align__(1024) __half g_act1[5 * PLANE];
__device__ __align__(1024) __half g_pre2[5 * PLANE];
__device__ __align__(1024) __half g_act2[5 * PLANE];
__device__ __align__(1024) __half g_w2h[(size_t)5 * HID * HID];
__device__ __align__(1024) __half g_w3h[(size_t)5 * OUTD * HID];
__device__ __align__(1024) float  g_out3[(size_t)5 * BROWS * OUTD];

// ---------------- orbit table ----------------
__constant__ int c_orbit[28] = {
    12, 0, 1, 2, 5, 6, 7,
    12, 4, 9, 14, 3, 8, 13,
    12, 24, 23, 22, 19, 18, 17,
    12, 20, 15, 10, 21, 16, 11
};

// ---------------- PTX helpers (baseline PTX only) ----------------
__device__ __forceinline__ uint32_t smem_u32(const void* p) {
    uint32_t a;
    asm("{ .reg .u64 t; cvta.to.shared.u64 t, %1; cvt.u32.u64 %0, t; }" : "=r"(a) : "l"(p));
    return a;
}
__device__ __forceinline__ void cp16(uint32_t d, const void* g) {
    asm volatile("cp.async.cg.shared.global [%0],[%1],16;\n" ::"r"(d), "l"(g));
}
#define LDSM4(r0, r1, r2, r3, addr) \
    asm volatile("ldmatrix.sync.aligned.m8n8.x4.shared.b16 {%0,%1,%2,%3},[%4];" \
                 : "=r"(r0), "=r"(r1), "=r"(r2), "=r"(r3) : "r"(addr))

__device__ __forceinline__ void mma16816(float* c, const uint32_t* a, uint32_t b0, uint32_t b1) {
    asm volatile(
        "mma.sync.aligned.m16n8k16.row.col.f32.f16.f16.f32 "
        "{%0,%1,%2,%3},{%4,%5,%6,%7},{%8,%9},{%0,%1,%2,%3};"
        : "+f"(c[0]), "+f"(c[1]), "+f"(c[2]), "+f"(c[3])
        : "r"(a[0]), "r"(a[1]), "r"(a[2]), "r"(a[3]), "r"(b0), "r"(b1));
}

// ---------------- weight combo prep ----------------
__global__ void wprep_kernel(const float* __restrict__ w2, const float* __restrict__ w3) {
    const size_t S2 = (size_t)HID * HID;
    const size_t S3 = (size_t)OUTD * HID;
    const size_t stride = (size_t)gridDim.x * blockDim.x;
    for (size_t i = (size_t)blockIdx.x * blockDim.x + threadIdx.x; i < S2; i += stride) {
        float a = w2[i], b = w2[S2 + i], c = w2[2 * S2 + i], d = w2[3 * S2 + i];
        g_w2h[0 * S2 + i] = __float2half(a + b + c + d);
        g_w2h[1 * S2 + i] = __float2half(a - b + c - d);
        g_w2h[2 * S2 + i] = __float2half(a - c);
        g_w2h[3 * S2 + i] = __float2half(-a + b + c - d);
        g_w2h[4 * S2 + i] = __float2half(a + b - c - d);
    }
    for (size_t i = (size_t)blockIdx.x * blockDim.x + threadIdx.x; i < S3; i += stride) {
        float a = w3[i], b = w3[S3 + i], c = w3[2 * S3 + i], d = w3[3 * S3 + i];
        g_w3h[0 * S3 + i] = __float2half(a + b + c + d);
        g_w3h[1 * S3 + i] = __float2half(a - b + c - d);
        g_w3h[2 * S3 + i] = __float2half(a - c);
        g_w3h[3 * S3 + i] = __float2half(-a + b + c - d);
        g_w3h[4 * S3 + i] = __float2half(a + b - c - d);
    }
}

// ---------------- layer 1: 4 rows per CTA ----------------
__global__ void layer1_kernel(const float* __restrict__ ins,
                              const float* __restrict__ w1,
                              const float* __restrict__ b1) {
    __shared__ float patch[4][25];
    __shared__ float feat[4][4][7];
    const int row0 = blockIdx.x * 4;
    const int t = threadIdx.x;

    if (t < 100) patch[t / 25][t % 25] = ins[(size_t)row0 * 25 + t];
    __syncthreads();
    if (t < 112) {
        const int r = t / 28, k = t % 28;
        feat[r][k / 7][k % 7] = patch[r][c_orbit[k]];
    }
    __syncthreads();

    for (int i = t; i < HID; i += 256) {
        const float bv = b1[i];
        float w[4][7];
        #pragma unroll
        for (int d = 0; d < 4; d++)
            #pragma unroll
            for (int j = 0; j < 7; j++)
                w[d][j] = w1[((size_t)d * HID + i) * 7 + j];

        #pragma unroll
        for (int r = 0; r < 4; r++) {
            float acc[4] = {bv, bv, bv, bv};
            #pragma unroll
            for (int d = 0; d < 4; d++) {
                #pragma unroll
                for (int g = 0; g < 4; g++) {
                    const float* f = feat[r][(g + d) & 3];
                    float a = 0.f;
                    #pragma unroll
                    for (int j = 0; j < 7; j++) a += w[d][j] * f[j];
                    acc[g] += a;
                }
            }
            const float r0 = fmaxf(acc[0], 0.f), r1 = fmaxf(acc[1], 0.f);
            const float r2 = fmaxf(acc[2], 0.f), r3 = fmaxf(acc[3], 0.f);
            const float xr = r0 - r2, xi = r3 - r1;
            const size_t off = (size_t)(row0 + r) * HID + i;
            g_act1[0 * PLANE + off] = __float2half(r0 + r1 + r2 + r3);
            g_act1[1 * PLANE + off] = __float2half(r0 - r1 + r2 - r3);
            g_act1[2 * PLANE + off] = __float2half(xr + xi);
            g_act1[3 * PLANE + off] = __float2half(xr);
            g_act1[4 * PLANE + off] = __float2half(xi);
        }
    }
}

// ---------------- batched GEMM: C[j] = A[j] @ B[j]^T  (j = 0..4) ----------------
// BM=256, BN=64, BK=32. 8 warps as 4 rows x 2 cols (warp tile 64x32).
// 80B row pitch (conflict-free LDSM without swizzle). 4-stage cp.async, 1 sync/iter.
static constexpr int APITCH = 80;                 // bytes per 32-half row
static constexpr int ASTAGE = 256 * APITCH;       // 20480
static constexpr int BSTAGE = 64 * APITCH;        // 5120
static constexpr int STAGE  = ASTAGE + BSTAGE;    // 25600
static constexpr int GEMM_SMEM = 4 * STAGE;       // 102400

template <int LAYER>
__global__ __launch_bounds__(256, 2)
void gemm_kernel() {
    constexpr int KT = HID / 32;  // 64
    constexpr size_t BSTRIDE = (LAYER == 2) ? (size_t)HID * HID : (size_t)OUTD * HID;
    constexpr int CP = (LAYER == 2) ? HID : OUTD;

    extern __shared__ char smem[];
    const uint32_t s0 = smem_u32(smem);

    const int tid = threadIdx.x;
    const int j = blockIdx.z;
    const int brow = blockIdx.y * 256;
    const int bcol = blockIdx.x * 64;

    const __half* Aall = (LAYER == 2) ? g_act1 : g_act2;
    const __half* Ball = (LAYER == 2) ? g_w2h : g_w3h;
    const char* Ag = (const char*)(Aall + (size_t)j * PLANE + (size_t)brow * HID);
    const char* Bg = (const char*)(Ball + (size_t)j * BSTRIDE + (size_t)bcol * HID);

    // loader mapping: A 1024 granules (4/thread), B 256 granules (1/thread)
    const int ar = tid >> 2, ag = tid & 3;   // A: rows tid>>2 + 64*i
    const int br = tid >> 2, bg = tid & 3;   // B: rows 0..63

    auto issue = [&](int st, int kt) {
        const uint32_t dA = s0 + st * STAGE;
        const uint32_t dB = dA + ASTAGE;
        const char* gA = Ag + (size_t)kt * 64;
        const char* gB = Bg + (size_t)kt * 64;
        #pragma unroll
        for (int i = 0; i < 4; i++) {
            const int r = ar + i * 64;
            cp16(dA + (uint32_t)r * APITCH + ag * 16,
                 gA + (size_t)r * (HID * 2) + ag * 16);
        }
        cp16(dB + (uint32_t)br * APITCH + bg * 16,
             gB + (size_t)br * (HID * 2) + bg * 16);
        asm volatile("cp.async.commit_group;\n");
    };

    issue(0, 0);
    issue(1, 1);
    issue(2, 2);

    const int warp = tid >> 5, lane = tid & 31;
    const int wm = (warp >> 1) * 64;               // 4 warp rows
    const int wn = (warp & 1) * 32;                // 2 warp cols
    const int rl = (lane & 7) + (((lane >> 3) & 1) << 3);  // 0..15
    const int hs = (lane >> 4) & 1;

    float acc[4][4][4];
    #pragma unroll
    for (int m = 0; m < 4; m++)
        #pragma unroll
        for (int n = 0; n < 4; n++)
            #pragma unroll
            for (int q = 0; q < 4; q++) acc[m][n][q] = 0.f;

    for (int kt = 0; kt < KT; kt++) {
        asm volatile("cp.async.wait_group 2;\n");
        __syncthreads();
        if (kt + 3 < KT) issue((kt + 3) & 3, kt + 3);
        else asm volatile("cp.async.commit_group;\n");

        const uint32_t stg = s0 + (kt & 3) * STAGE;
        const uint32_t aBase = stg + (uint32_t)(wm + rl) * APITCH;
        const uint32_t bBase = stg + ASTAGE + (uint32_t)(wn + rl) * APITCH;

        #pragma unroll
        for (int kk = 0; kk < 2; kk++) {
            const uint32_t goff = (uint32_t)((kk * 2 + hs) * 16);
            uint32_t a[4][4], b[2][4];
            #pragma unroll
            for (int m = 0; m < 4; m++)
                LDSM4(a[m][0], a[m][1], a[m][2], a[m][3],
                      aBase + (uint32_t)(m * 16 * APITCH) + goff);
            #pragma unroll
            for (int n2 = 0; n2 < 2; n2++)
                LDSM4(b[n2][0], b[n2][1], b[n2][2], b[n2][3],
                      bBase + (uint32_t)(n2 * 16 * APITCH) + goff);
            #pragma unroll
            for (int m = 0; m < 4; m++) {
                #pragma unroll
                for (int n2 = 0; n2 < 2; n2++) {
                    mma16816(acc[m][n2 * 2 + 0], a[m], b[n2][0], b[n2][2]);
                    mma16816(acc[m][n2 * 2 + 1], a[m], b[n2][1], b[n2][3]);
                }
            }
        }
    }

    // ---- epilogue ----
    const int r0 = lane >> 2, cql = (lane & 3) * 2;
    #pragma unroll
    for (int m = 0; m < 4; m++) {
        #pragma unroll
        for (int jn = 0; jn < 4; jn++) {
            const size_t row = (size_t)brow + wm + m * 16 + r0;
            const int col = bcol + wn + (jn >> 1) * 16 + (jn & 1) * 8 + cql;
            if (LAYER == 2) {
                __half* C = g_pre2 + (size_t)j * PLANE;
                *(__half2*)&C[row * CP + col] =
                    __floats2half2_rn(acc[m][jn][0], acc[m][jn][1]);
                *(__half2*)&C[(row + 8) * CP + col] =
                    __floats2half2_rn(acc[m][jn][2], acc[m][jn][3]);
            } else {
                float* C = g_out3 + (size_t)j * ((size_t)BROWS * OUTD);
                *(float2*)&C[row * CP + col] = make_float2(acc[m][jn][0], acc[m][jn][1]);
                *(float2*)&C[(row + 8) * CP + col] = make_float2(acc[m][jn][2], acc[m][jn][3]);
            }
        }
    }
}

// ---------------- inverse DFT + bias + LN + relu + forward DFT ----------------
__global__ void ln_tf_kernel(const float* __restrict__ b2,
                             const float* __restrict__ lng,
                             const float* __restrict__ lnb) {
    const size_t rf = blockIdx.x;
    const int t = threadIdx.x;
    const size_t off = rf * HID;
    const int c0 = t * 8;

    float P[5][8];
    #pragma unroll
    for (int jp = 0; jp < 5; jp++) {
        float4 v = *((const float4*)(g_pre2 + jp * PLANE + off) + t);
        const __half2* h = (const __half2*)&v;
        #pragma unroll
        for (int k = 0; k < 4; k++) {
            float2 f = __half22float2(h[k]);
            P[jp][2 * k] = f.x;
            P[jp][2 * k + 1] = f.y;
        }
    }

    float y[4][8];
    float s[4] = {0.f, 0.f, 0.f, 0.f}, q[4] = {0.f, 0.f, 0.f, 0.f};
    #pragma unroll
    for (int k = 0; k < 8; k++) {
        const float yr = P[2][k] - P[4][k];
        const float yi = P[2][k] + P[3][k];
        const float bb = __ldg(&b2[c0 + k]);
        const float e = P[0][k] + P[1][k], o = P[0][k] - P[1][k];
        y[0][k] = 0.25f * (e + 2.f * yr) + bb;
        y[1][k] = 0.25f * (o - 2.f * yi) + bb;
        y[2][k] = 0.25f * (e - 2.f * yr) + bb;
        y[3][k] = 0.25f * (o + 2.f * yi) + bb;
        #pragma unroll
        for (int g = 0; g < 4; g++) { s[g] += y[g][k]; q[g] += y[g][k] * y[g][k]; }
    }

    __shared__ float ss[4][8], qq[4][8];
    const int warp = t >> 5, lane = t & 31;
    #pragma unroll
    for (int g = 0; g < 4; g++) {
        #pragma unroll
        for (int o = 16; o > 0; o >>= 1) {
            s[g] += __shfl_down_sync(0xffffffffu, s[g], o);
            q[g] += __shfl_down_sync(0xffffffffu, q[g], o);
        }
        if (lane == 0) { ss[g][warp] = s[g]; qq[g][warp] = q[g]; }
    }
    __syncthreads();
    __shared__ float mean[4], rstd[4];
    if (t < 4) {
        float a = 0.f, b = 0.f;
        #pragma unroll
        for (int w = 0; w < 8; w++) { a += ss[t][w]; b += qq[t][w]; }
        const float m = a * (1.f / HID);
        mean[t] = m;
        rstd[t] = rsqrtf(b * (1.f / HID) - m * m + 1e-5f);
    }
    __syncthreads();

    float r[4][8];
    #pragma unroll
    for (int k = 0; k < 8; k++) {
        const float gv = __ldg(&lng[c0 + k]), bv = __ldg(&lnb[c0 + k]);
        #pragma unroll
        for (int g = 0; g < 4; g++)
            r[g][k] = fmaxf((y[g][k] - mean[g]) * rstd[g] * gv + bv, 0.f);
    }

    float Z[5][8];
    #pragma unroll
    for (int k = 0; k < 8; k++) {
        const float zr = r[0][k] - r[2][k], zi = r[3][k] - r[1][k];
        Z[0][k] = r[0][k] + r[1][k] + r[2][k] + r[3][k];
        Z[1][k] = r[0][k] - r[1][k] + r[2][k] - r[3][k];
        Z[2][k] = zr + zi;
        Z[3][k] = zr;
        Z[4][k] = zi;
    }
    #pragma unroll
    for (int jp = 0; jp < 5; jp++) {
        float4 v;
        __half2* h = (__half2*)&v;
        #pragma unroll
        for (int k = 0; k < 4; k++)
            h[k] = __floats2half2_rn(Z[jp][2 * k], Z[jp][2 * k + 1]);
        *((float4*)(g_act2 + jp * PLANE + off) + t) = v;
    }
}

// ---------------- final: inverse DFT + bias b3 -> out ----------------
__global__ void combine3_kernel(const float* __restrict__ b3, float* __restrict__ out) {
    const size_t row = blockIdx.x;
    const int t = threadIdx.x;
    const int g = t >> 6;
    const int c0 = (t & 63) * 8;
    const size_t poff = row * OUTD + c0;

    float P[5][8];
    #pragma unroll
    for (int jp = 0; jp < 5; jp++) {
        const float* src = g_out3 + (size_t)jp * ((size_t)BROWS * OUTD) + poff;
        *(float4*)&P[jp][0] = *(const float4*)&src[0];
        *(float4*)&P[jp][4] = *(const float4*)&src[4];
    }
    float o[8];
    #pragma unroll
    for (int k = 0; k < 8; k++) {
        const float yr = P[2][k] - P[4][k];
        const float yi = P[2][k] + P[3][k];
        const float e = P[0][k] + P[1][k], od = P[0][k] - P[1][k];
        float v;
        if (g == 0)      v = 0.25f * (e + 2.f * yr);
        else if (g == 1) v = 0.25f * (od - 2.f * yi);
        else if (g == 2) v = 0.25f * (e - 2.f * yr);
        else             v = 0.25f * (od + 2.f * yi);
        o[k] = v + __ldg(&b3[c0 + k]);
    }
    float* dst = out + row * 2048 + (size_t)g * OUTD + c0;
    *(float4*)&dst[0] = *(const float4*)&o[0];
    *(float4*)&dst[4] = *(const float4*)&o[4];
}

// ---------------- launch ----------------
extern "C" void kernel_launch(void* const* d_in, const int* in_sizes, int n_in,
                              void* d_out, int out_size) {
    const float* ins = (const float*)d_in[0];
    const float* w1 = (const float*)d_in[1];
    const float* b1 = (const float*)d_in[2];
    const float* w2 = (const float*)d_in[3];
    const float* b2 = (const float*)d_in[4];
    const float* w3 = (const float*)d_in[5];
    const float* b3 = (const float*)d_in[6];
    const float* lng = (const float*)d_in[7];
    const float* lnb = (const float*)d_in[8];
    float* out = (float*)d_out;

    cudaFuncSetAttribute(gemm_kernel<2>, cudaFuncAttributeMaxDynamicSharedMemorySize, GEMM_SMEM);
    cudaFuncSetAttribute(gemm_kernel<3>, cudaFuncAttributeMaxDynamicSharedMemorySize, GEMM_SMEM);

    wprep_kernel<<<2048, 256>>>(w2, w3);
    layer1_kernel<<<BROWS / 4, 256>>>(ins, w1, b1);

    {
        dim3 grid(HID / 64, BROWS / 256, 5);    // (32, 40, 5)
        gemm_kernel<2><<<grid, 256, GEMM_SMEM>>>();
    }
    ln_tf_kernel<<<BROWS, 256>>>(b2, lng, lnb);
    {
        dim3 grid(OUTD / 64, BROWS / 256, 5);   // (8, 40, 5)
        gemm_kernel<3><<<grid, 256, GEMM_SMEM>>>();
    }
    combine3_kernel<<<BROWS, 256>>>(b3, out);
}

// round 6
// speedup vs baseline: 1.3847x; 1.3847x over previous
#include <cuda_runtime.h>
#include <cuda_fp16.h>
#include <cstdint>

// ---------------- problem constants ----------------
#define BROWS 10240          // B*N = 2048*5
#define HID   2048
#define OUTD  512
#define PLANE ((size_t)BROWS * HID)

// ---------------- persistent device scratch ----------------
// 5 DFT planes: [0]=X0, [1]=X2, [2]=Xs(=Xr+Xi), [3]=Xr, [4]=Xi
__device__ __align__(1024) __half g_act1[5 * PLANE];
__device__ __align__(1024) __half g_pre2[5 * PLANE];
__device__ __align__(1024) __half g_act2[5 * PLANE];
__device__ __align__(1024) __half g_w2h[(size_t)5 * HID * HID];
__device__ __align__(1024) __half g_w3h[(size_t)5 * OUTD * HID];
__device__ __align__(1024) float  g_out3[(size_t)5 * BROWS * OUTD];

// ---------------- orbit table ----------------
__constant__ int c_orbit[28] = {
    12, 0, 1, 2, 5, 6, 7,
    12, 4, 9, 14, 3, 8, 13,
    12, 24, 23, 22, 19, 18, 17,
    12, 20, 15, 10, 21, 16, 11
};

// ---------------- PTX helpers (baseline PTX only) ----------------
__device__ __forceinline__ uint32_t smem_u32(const void* p) {
    uint32_t a;
    asm("{ .reg .u64 t; cvta.to.shared.u64 t, %1; cvt.u32.u64 %0, t; }" : "=r"(a) : "l"(p));
    return a;
}
__device__ __forceinline__ void cp16(uint32_t d, const void* g) {
    asm volatile("cp.async.cg.shared.global [%0],[%1],16;\n" ::"r"(d), "l"(g));
}
#define LDSM4(r0, r1, r2, r3, addr) \
    asm volatile("ldmatrix.sync.aligned.m8n8.x4.shared.b16 {%0,%1,%2,%3},[%4];" \
                 : "=r"(r0), "=r"(r1), "=r"(r2), "=r"(r3) : "r"(addr))

__device__ __forceinline__ void mma16816(float* c, const uint32_t* a, uint32_t b0, uint32_t b1) {
    asm volatile(
        "mma.sync.aligned.m16n8k16.row.col.f32.f16.f16.f32 "
        "{%0,%1,%2,%3},{%4,%5,%6,%7},{%8,%9},{%0,%1,%2,%3};"
        : "+f"(c[0]), "+f"(c[1]), "+f"(c[2]), "+f"(c[3])
        : "r"(a[0]), "r"(a[1]), "r"(a[2]), "r"(a[3]), "r"(b0), "r"(b1));
}

// ---------------- weight combo prep ----------------
__global__ void wprep_kernel(const float* __restrict__ w2, const float* __restrict__ w3) {
    const size_t S2 = (size_t)HID * HID;
    const size_t S3 = (size_t)OUTD * HID;
    const size_t stride = (size_t)gridDim.x * blockDim.x;
    for (size_t i = (size_t)blockIdx.x * blockDim.x + threadIdx.x; i < S2; i += stride) {
        float a = w2[i], b = w2[S2 + i], c = w2[2 * S2 + i], d = w2[3 * S2 + i];
        g_w2h[0 * S2 + i] = __float2half(a + b + c + d);
        g_w2h[1 * S2 + i] = __float2half(a - b + c - d);
        g_w2h[2 * S2 + i] = __float2half(a - c);
        g_w2h[3 * S2 + i] = __float2half(-a + b + c - d);
        g_w2h[4 * S2 + i] = __float2half(a + b - c - d);
    }
    for (size_t i = (size_t)blockIdx.x * blockDim.x + threadIdx.x; i < S3; i += stride) {
        float a = w3[i], b = w3[S3 + i], c = w3[2 * S3 + i], d = w3[3 * S3 + i];
        g_w3h[0 * S3 + i] = __float2half(a + b + c + d);
        g_w3h[1 * S3 + i] = __float2half(a - b + c - d);
        g_w3h[2 * S3 + i] = __float2half(a - c);
        g_w3h[3 * S3 + i] = __float2half(-a + b + c - d);
        g_w3h[4 * S3 + i] = __float2half(a + b - c - d);
    }
}

// ---------------- layer 1: 4 rows per CTA ----------------
__global__ void layer1_kernel(const float* __restrict__ ins,
                              const float* __restrict__ w1,
                              const float* __restrict__ b1) {
    __shared__ float patch[4][25];
    __shared__ float feat[4][4][7];
    const int row0 = blockIdx.x * 4;
    const int t = threadIdx.x;

    if (t < 100) patch[t / 25][t % 25] = ins[(size_t)row0 * 25 + t];
    __syncthreads();
    if (t < 112) {
        const int r = t / 28, k = t % 28;
        feat[r][k / 7][k % 7] = patch[r][c_orbit[k]];
    }
    __syncthreads();

    for (int i = t; i < HID; i += 256) {
        const float bv = b1[i];
        float w[4][7];
        #pragma unroll
        for (int d = 0; d < 4; d++)
            #pragma unroll
            for (int j = 0; j < 7; j++)
                w[d][j] = w1[((size_t)d * HID + i) * 7 + j];

        #pragma unroll
        for (int r = 0; r < 4; r++) {
            float acc[4] = {bv, bv, bv, bv};
            #pragma unroll
            for (int d = 0; d < 4; d++) {
                #pragma unroll
                for (int g = 0; g < 4; g++) {
                    const float* f = feat[r][(g + d) & 3];
                    float a = 0.f;
                    #pragma unroll
                    for (int j = 0; j < 7; j++) a += w[d][j] * f[j];
                    acc[g] += a;
                }
            }
            const float r0 = fmaxf(acc[0], 0.f), r1 = fmaxf(acc[1], 0.f);
            const float r2 = fmaxf(acc[2], 0.f), r3 = fmaxf(acc[3], 0.f);
            const float xr = r0 - r2, xi = r3 - r1;
            const size_t off = (size_t)(row0 + r) * HID + i;
            g_act1[0 * PLANE + off] = __float2half(r0 + r1 + r2 + r3);
            g_act1[1 * PLANE + off] = __float2half(r0 - r1 + r2 - r3);
            g_act1[2 * PLANE + off] = __float2half(xr + xi);
            g_act1[3 * PLANE + off] = __float2half(xr);
            g_act1[4 * PLANE + off] = __float2half(xi);
        }
    }
}

// ---------------- batched GEMM: C[j] = A[j] @ B[j]^T  (j = 0..4) ----------------
// R3 geometry: BM=BN=128, BK=64, 3-stage cp.async, XOR swizzle, 2 CTA/SM.
// R6 changes: single __syncthreads per K-iter; cp.async issue placed mid-iter.
static constexpr int GEMM_SMEM = 3 * 16384 * 2;  // 98304

template <int LAYER>
__global__ __launch_bounds__(256, 2)
void gemm_kernel() {
    constexpr int BK = 64;
    constexpr int KT = HID / BK;  // 32
    constexpr size_t BSTRIDE = (LAYER == 2) ? (size_t)HID * HID : (size_t)OUTD * HID;
    constexpr int CP = (LAYER == 2) ? HID : OUTD;

    extern __shared__ char smem[];
    const uint32_t sA = smem_u32(smem);            // [3][16KB]
    const uint32_t sB = sA + 3 * 16384;            // [3][16KB]

    const int tid = threadIdx.x;
    const int j = blockIdx.z;
    const int brow = blockIdx.y * 128;
    const int bcol = blockIdx.x * 128;

    const __half* Aall = (LAYER == 2) ? g_act1 : g_act2;
    const __half* Ball = (LAYER == 2) ? g_w2h : g_w3h;
    const char* Ag = (const char*)(Aall + (size_t)j * PLANE + (size_t)brow * HID);
    const char* Bg = (const char*)(Ball + (size_t)j * BSTRIDE + (size_t)bcol * HID);

    // loader mapping: thread t -> 16B group lg of rows lr0 + 32*i
    const int lg = tid & 7;
    const int lr0 = tid >> 3;

    auto issue = [&](int st, int kt) {
        const uint32_t dA = sA + st * 16384, dB = sB + st * 16384;
        const char* gA = Ag + (size_t)kt * 128;
        const char* gB = Bg + (size_t)kt * 128;
        #pragma unroll
        for (int i = 0; i < 4; i++) {
            const int r = lr0 + i * 32;
            const uint32_t ph = (uint32_t)r * 128 + (uint32_t)((lg ^ (r & 7)) * 16);
            cp16(dA + ph, gA + (size_t)r * (HID * 2) + lg * 16);
            cp16(dB + ph, gB + (size_t)r * (HID * 2) + lg * 16);
        }
        asm volatile("cp.async.commit_group;\n");
    };

    issue(0, 0);
    issue(1, 1);

    const int warp = tid >> 5, lane = tid & 31;
    const int wm = (warp >> 2) * 64;   // 2 warp rows
    const int wn = (warp & 3) * 32;    // 4 warp cols
    const int rl = (lane & 7) + (((lane >> 3) & 1) << 3);  // 0..15
    const int hs = (lane >> 4) & 1;
    const int sw = lane & 7;

    float acc[4][4][4];
    #pragma unroll
    for (int m = 0; m < 4; m++)
        #pragma unroll
        for (int n = 0; n < 4; n++)
            #pragma unroll
            for (int q = 0; q < 4; q++) acc[m][n][q] = 0.f;

    for (int kt = 0; kt < KT; kt++) {
        asm volatile("cp.async.wait_group 1;\n");
        __syncthreads();   // single barrier: fences prev-iter readers of stage (kt+2)%3

        const int st = kt % 3;
        const uint32_t aBase = sA + st * 16384 + (uint32_t)(wm + rl) * 128;
        const uint32_t bBase = sB + st * 16384 + (uint32_t)(wn + rl) * 128;

        #pragma unroll
        for (int kk = 0; kk < 4; kk++) {
            const uint32_t goff = (uint32_t)(((kk * 2 + hs) ^ sw) * 16);
            uint32_t a[4][4], b[2][4];
            #pragma unroll
            for (int m = 0; m < 4; m++)
                LDSM4(a[m][0], a[m][1], a[m][2], a[m][3], aBase + m * 16 * 128 + goff);
            #pragma unroll
            for (int n2 = 0; n2 < 2; n2++)
                LDSM4(b[n2][0], b[n2][1], b[n2][2], b[n2][3], bBase + n2 * 16 * 128 + goff);
            #pragma unroll
            for (int m = 0; m < 4; m++) {
                #pragma unroll
                for (int n2 = 0; n2 < 2; n2++) {
                    mma16816(acc[m][n2 * 2 + 0], a[m], b[n2][0], b[n2][2]);
                    mma16816(acc[m][n2 * 2 + 1], a[m], b[n2][1], b[n2][3]);
                }
            }
            // mid-iter issue: after first kk block, fire next stage's loads.
            // Target stage (kt+2)%3 == (kt-1)%3 is disjoint from current readers;
            // the top-of-iter sync already fenced last iter's readers of it.
            if (kk == 0) {
                if (kt + 2 < KT) issue((kt + 2) % 3, kt + 2);
                else asm volatile("cp.async.commit_group;\n");
            }
        }
    }

    // ---- epilogue ----
    const int r0 = lane >> 2, cql = (lane & 3) * 2;
    #pragma unroll
    for (int m = 0; m < 4; m++) {
        #pragma unroll
        for (int jn = 0; jn < 4; jn++) {
            const size_t row = (size_t)brow + wm + m * 16 + r0;
            const int col = bcol + wn + (jn >> 1) * 16 + (jn & 1) * 8 + cql;
            if (LAYER == 2) {
                __half* C = g_pre2 + (size_t)j * PLANE;
                *(__half2*)&C[row * CP + col] =
                    __floats2half2_rn(acc[m][jn][0], acc[m][jn][1]);
                *(__half2*)&C[(row + 8) * CP + col] =
                    __floats2half2_rn(acc[m][jn][2], acc[m][jn][3]);
            } else {
                float* C = g_out3 + (size_t)j * ((size_t)BROWS * OUTD);
                *(float2*)&C[row * CP + col] = make_float2(acc[m][jn][0], acc[m][jn][1]);
                *(float2*)&C[(row + 8) * CP + col] = make_float2(acc[m][jn][2], acc[m][jn][3]);
            }
        }
    }
}

// ---------------- inverse DFT + bias + LN + relu + forward DFT ----------------
__global__ void ln_tf_kernel(const float* __restrict__ b2,
                             const float* __restrict__ lng,
                             const float* __restrict__ lnb) {
    const size_t rf = blockIdx.x;
    const int t = threadIdx.x;
    const size_t off = rf * HID;
    const int c0 = t * 8;

    float P[5][8];
    #pragma unroll
    for (int jp = 0; jp < 5; jp++) {
        float4 v = *((const float4*)(g_pre2 + jp * PLANE + off) + t);
        const __half2* h = (const __half2*)&v;
        #pragma unroll
        for (int k = 0; k < 4; k++) {
            float2 f = __half22float2(h[k]);
            P[jp][2 * k] = f.x;
            P[jp][2 * k + 1] = f.y;
        }
    }

    float y[4][8];
    float s[4] = {0.f, 0.f, 0.f, 0.f}, q[4] = {0.f, 0.f, 0.f, 0.f};
    #pragma unroll
    for (int k = 0; k < 8; k++) {
        const float yr = P[2][k] - P[4][k];
        const float yi = P[2][k] + P[3][k];
        const float bb = __ldg(&b2[c0 + k]);
        const float e = P[0][k] + P[1][k], o = P[0][k] - P[1][k];
        y[0][k] = 0.25f * (e + 2.f * yr) + bb;
        y[1][k] = 0.25f * (o - 2.f * yi) + bb;
        y[2][k] = 0.25f * (e - 2.f * yr) + bb;
        y[3][k] = 0.25f * (o + 2.f * yi) + bb;
        #pragma unroll
        for (int g = 0; g < 4; g++) { s[g] += y[g][k]; q[g] += y[g][k] * y[g][k]; }
    }

    __shared__ float ss[4][8], qq[4][8];
    const int warp = t >> 5, lane = t & 31;
    #pragma unroll
    for (int g = 0; g < 4; g++) {
        #pragma unroll
        for (int o = 16; o > 0; o >>= 1) {
            s[g] += __shfl_down_sync(0xffffffffu, s[g], o);
            q[g] += __shfl_down_sync(0xffffffffu, q[g], o);
        }
        if (lane == 0) { ss[g][warp] = s[g]; qq[g][warp] = q[g]; }
    }
    __syncthreads();
    __shared__ float mean[4], rstd[4];
    if (t < 4) {
        float a = 0.f, b = 0.f;
        #pragma unroll
        for (int w = 0; w < 8; w++) { a += ss[t][w]; b += qq[t][w]; }
        const float m = a * (1.f / HID);
        mean[t] = m;
        rstd[t] = rsqrtf(b * (1.f / HID) - m * m + 1e-5f);
    }
    __syncthreads();

    float r[4][8];
    #pragma unroll
    for (int k = 0; k < 8; k++) {
        const float gv = __ldg(&lng[c0 + k]), bv = __ldg(&lnb[c0 + k]);
        #pragma unroll
        for (int g = 0; g < 4; g++)
            r[g][k] = fmaxf((y[g][k] - mean[g]) * rstd[g] * gv + bv, 0.f);
    }

    float Z[5][8];
    #pragma unroll
    for (int k = 0; k < 8; k++) {
        const float zr = r[0][k] - r[2][k], zi = r[3][k] - r[1][k];
        Z[0][k] = r[0][k] + r[1][k] + r[2][k] + r[3][k];
        Z[1][k] = r[0][k] - r[1][k] + r[2][k] - r[3][k];
        Z[2][k] = zr + zi;
        Z[3][k] = zr;
        Z[4][k] = zi;
    }
    #pragma unroll
    for (int jp = 0; jp < 5; jp++) {
        float4 v;
        __half2* h = (__half2*)&v;
        #pragma unroll
        for (int k = 0; k < 4; k++)
            h[k] = __floats2half2_rn(Z[jp][2 * k], Z[jp][2 * k + 1]);
        *((float4*)(g_act2 + jp * PLANE + off) + t) = v;
    }
}

// ---------------- final: inverse DFT + bias b3 -> out ----------------
__global__ void combine3_kernel(const float* __restrict__ b3, float* __restrict__ out) {
    const size_t row = blockIdx.x;
    const int t = threadIdx.x;
    const int g = t >> 6;
    const int c0 = (t & 63) * 8;
    const size_t poff = row * OUTD + c0;

    float P[5][8];
    #pragma unroll
    for (int jp = 0; jp < 5; jp++) {
        const float* src = g_out3 + (size_t)jp * ((size_t)BROWS * OUTD) + poff;
        *(float4*)&P[jp][0] = *(const float4*)&src[0];
        *(float4*)&P[jp][4] = *(const float4*)&src[4];
    }
    float o[8];
    #pragma unroll
    for (int k = 0; k < 8; k++) {
        const float yr = P[2][k] - P[4][k];
        const float yi = P[2][k] + P[3][k];
        const float e = P[0][k] + P[1][k], od = P[0][k] - P[1][k];
        float v;
        if (g == 0)      v = 0.25f * (e + 2.f * yr);
        else if (g == 1) v = 0.25f * (od - 2.f * yi);
        else if (g == 2) v = 0.25f * (e - 2.f * yr);
        else             v = 0.25f * (od + 2.f * yi);
        o[k] = v + __ldg(&b3[c0 + k]);
    }
    float* dst = out + row * 2048 + (size_t)g * OUTD + c0;
    *(float4*)&dst[0] = *(const float4*)&o[0];
    *(float4*)&dst[4] = *(const float4*)&o[4];
}

// ---------------- launch ----------------
extern "C" void kernel_launch(void* const* d_in, const int* in_sizes, int n_in,
                              void* d_out, int out_size) {
    const float* ins = (const float*)d_in[0];
    const float* w1 = (const float*)d_in[1];
    const float* b1 = (const float*)d_in[2];
    const float* w2 = (const float*)d_in[3];
    const float* b2 = (const float*)d_in[4];
    const float* w3 = (const float*)d_in[5];
    const float* b3 = (const float*)d_in[6];
    const float* lng = (const float*)d_in[7];
    const float* lnb = (const float*)d_in[8];
    float* out = (float*)d_out;

    cudaFuncSetAttribute(gemm_kernel<2>, cudaFuncAttributeMaxDynamicSharedMemorySize, GEMM_SMEM);
    cudaFuncSetAttribute(gemm_kernel<3>, cudaFuncAttributeMaxDynamicSharedMemorySize, GEMM_SMEM);

    wprep_kernel<<<2048, 256>>>(w2, w3);
    layer1_kernel<<<BROWS / 4, 256>>>(ins, w1, b1);

    {
        dim3 grid(HID / 128, BROWS / 128, 5);   // (16, 80, 5)
        gemm_kernel<2><<<grid, 256, GEMM_SMEM>>>();
    }
    ln_tf_kernel<<<BROWS, 256>>>(b2, lng, lnb);
    {
        dim3 grid(OUTD / 128, BROWS / 128, 5);  // (4, 80, 5)
        gemm_kernel<3><<<grid, 256, GEMM_SMEM>>>();
    }
    combine3_kernel<<<BROWS, 256>>>(b3, out);
}